// round 3
// baseline (speedup 1.0000x reference)
#include <cuda_runtime.h>

#define B  32
#define L  1024
#define D  512
#define NN 512

// scratch: per-(batch, dim) mean difference (mean_l i - mean_l j)
__device__ float g_md[B * D];

// ---------------------------------------------------------------------------
// Kernel 1: md[b,d] = (1/L) * sum_l (i[b,l,d] - j[b,l,d])
// Grid: B * (D/64) = 256 blocks. Block: 256 threads.
//   tid -> dq = tid & 15   (float4 index within the 64-float d-tile)
//          lg = tid >> 4   (16 l-groups, each sums L/16 = 64 rows)
// Fully coalesced float4 loads; 128 independent loads in flight per thread
// group via unrolling -> HBM-bound.
// ---------------------------------------------------------------------------
__global__ void __launch_bounds__(256) mean_diff_kernel(
    const float* __restrict__ gi, const float* __restrict__ gj)
{
    const int blk = blockIdx.x;
    const int b   = blk >> 3;       // batch
    const int dt  = blk & 7;        // 64-float d tile (8 per D=512)
    const int tid = threadIdx.x;
    const int dq  = tid & 15;       // float4 within tile
    const int lg  = tid >> 4;       // l-group

    const int rowq = D / 4;         // 128 float4 per row
    const float4* pi = (const float4*)(gi + (size_t)b * L * D) + dt * 16 + dq;
    const float4* pj = (const float4*)(gj + (size_t)b * L * D) + dt * 16 + dq;

    float4 acc = make_float4(0.f, 0.f, 0.f, 0.f);
    #pragma unroll 8
    for (int l = lg; l < L; l += 16) {
        float4 a = pi[(size_t)l * rowq];
        float4 c = pj[(size_t)l * rowq];
        acc.x += a.x - c.x;
        acc.y += a.y - c.y;
        acc.z += a.z - c.z;
        acc.w += a.w - c.w;
    }

    __shared__ float4 s[256];
    s[tid] = acc;
    __syncthreads();

    // tree-reduce over the 16 l-groups (same dq lanes are 16 apart)
    #pragma unroll
    for (int stride = 128; stride >= 16; stride >>= 1) {
        if (tid < stride) {
            float4 o = s[tid + stride];
            s[tid].x += o.x; s[tid].y += o.y; s[tid].z += o.z; s[tid].w += o.w;
        }
        __syncthreads();
    }

    if (tid < 16) {
        const float inv = 1.0f / (float)L;
        float4 r = s[tid];
        float4 out = make_float4(r.x * inv, r.y * inv, r.z * inv, r.w * inv);
        ((float4*)(g_md + b * D + dt * 64))[tid] = out;
    }
}

// ---------------------------------------------------------------------------
// Kernel 2: u[b,n] = sum_d md[b,d] * W[d,n];
//           out[b,n] = 0.5*(relu(u + bias[n]) + relu(bias[n] - u))
// Grid: B * (NN/128) = 128 blocks. Block: 512 threads.
//   tid -> nloc = tid & 127 (output column within 128-wide tile)
//          dg   = tid >> 7  (4 d-groups of 128 each)
// W reads coalesced along n; md staged in shared; 4 partials reduced in smem.
// ---------------------------------------------------------------------------
__global__ void __launch_bounds__(512) gemv_combine_kernel(
    const float* __restrict__ W, const float* __restrict__ bias,
    float* __restrict__ out)
{
    const int blk  = blockIdx.x;
    const int b    = blk >> 2;      // batch
    const int nt   = blk & 3;       // 128-wide n tile
    const int tid  = threadIdx.x;
    const int nloc = tid & 127;
    const int dg   = tid >> 7;      // d-group 0..3

    __shared__ float smd[D];
    smd[tid] = g_md[b * D + tid];   // 512 threads cover D=512
    __syncthreads();

    const int n = nt * 128 + nloc;
    const float* Wp = W + (size_t)(dg * 128) * NN + n;

    float u = 0.f;
    #pragma unroll 16
    for (int d = 0; d < 128; d++)
        u = fmaf(smd[dg * 128 + d], Wp[(size_t)d * NN], u);

    __shared__ float su[512];
    su[tid] = u;
    __syncthreads();

    if (tid < 128) {
        float t  = su[tid] + su[tid + 128] + su[tid + 256] + su[tid + 384];
        float bb = bias[nt * 128 + tid];
        out[b * NN + nt * 128 + tid] =
            0.5f * (fmaxf(t + bb, 0.f) + fmaxf(bb - t, 0.f));
    }
}

extern "C" void kernel_launch(void* const* d_in, const int* in_sizes, int n_in,
                              void* d_out, int out_size)
{
    const float* gi   = (const float*)d_in[0];   // i     [B, L, D]
    const float* gj   = (const float*)d_in[1];   // j     [B, L, D]
    const float* W    = (const float*)d_in[2];   // W_agg [D, NN]
    const float* bias = (const float*)d_in[3];   // b_agg [NN]
    float* out = (float*)d_out;                  // [B, NN]

    mean_diff_kernel<<<B * (D / 64), 256>>>(gi, gj);
    gemv_combine_kernel<<<B * (NN / 128), 512>>>(W, bias, out);
}

// round 4
// speedup vs baseline: 1.2062x; 1.2062x over previous
#include <cuda_runtime.h>

#define B  32
#define L  1024
#define D  512
#define NN 512

// 4 partial-sum planes of sum_l(i - j) over L-quarters: [4][B][D]
__device__ float g_part[4 * B * D];
// DCE-defeating sink for the W prefetch
__device__ float g_sink;

// ---------------------------------------------------------------------------
// Kernel 1: partial[lq][b][d] = sum_{l in quarter lq} (i[b,l,d] - j[b,l,d])
// Grid: B * 8(d-tiles) * 4(l-quarters) = 1024 blocks (6.9 waves on 148 SMs).
// Block: 256 threads; dq = tid&15 (float4 within 64-float d-tile),
//                     lg = tid>>4 (16 groups x 16 rows = 256 rows/quarter).
// i/j loaded with __ldcs (evict-first) so the 128MB stream does not evict W.
// Side job: collectively prefetch W (1 MB) into L2 with __ldcg — overlapped
// with the streaming loads, so kernel 2 hits L2 instead of cold DRAM.
// ---------------------------------------------------------------------------
__global__ void __launch_bounds__(256) mean_diff_kernel(
    const float* __restrict__ gi, const float* __restrict__ gj,
    const float* __restrict__ W)
{
    const int blk = blockIdx.x;
    const int b   = blk >> 5;         // batch
    const int r   = blk & 31;
    const int dt  = r >> 2;           // 64-float d tile (8 per D)
    const int lq  = r & 3;            // L quarter
    const int tid = threadIdx.x;
    const int dq  = tid & 15;
    const int lg  = tid >> 4;

    // --- W prefetch: 1024 blocks x 64 float4 = 1 MB, keep in L2 ---
    if (tid < 64) {
        float4 w = __ldcg(((const float4*)W) + blk * 64 + tid);
        float t = w.x + w.y + w.z + w.w;
        if (__float_as_int(t) == 0x7f800001)  // never true in practice, not provable
            g_sink = t;
    }

    const int rowq = D / 4;           // 128 float4 per row
    const float4* pi = (const float4*)(gi + (size_t)b * L * D) + dt * 16 + dq;
    const float4* pj = (const float4*)(gj + (size_t)b * L * D) + dt * 16 + dq;

    const int l0 = lq * 256 + lg * 16;
    float4 acc = make_float4(0.f, 0.f, 0.f, 0.f);
    #pragma unroll
    for (int rr = 0; rr < 16; rr++) {
        size_t off = (size_t)(l0 + rr) * rowq;
        float4 a = __ldcs(pi + off);
        float4 c = __ldcs(pj + off);
        acc.x += a.x - c.x;
        acc.y += a.y - c.y;
        acc.z += a.z - c.z;
        acc.w += a.w - c.w;
    }

    __shared__ float4 s[256];
    s[tid] = acc;
    __syncthreads();

    #pragma unroll
    for (int stride = 128; stride >= 16; stride >>= 1) {
        if (tid < stride) {
            float4 o = s[tid + stride];
            s[tid].x += o.x; s[tid].y += o.y; s[tid].z += o.z; s[tid].w += o.w;
        }
        __syncthreads();
    }

    if (tid < 16)
        ((float4*)(g_part + lq * B * D + b * D + dt * 64))[tid] = s[tid];
}

// ---------------------------------------------------------------------------
// Kernel 2: u[b,n] = (1/L) * sum_d (sum_lq part[lq][b][d]) * W[d,n]
//           out[b,n] = 0.5*(relu(u + bias[n]) + relu(bias[n] - u))
// Grid: B * 8(n-tiles of 64) = 256 blocks. Block: 512 threads.
//   nloc = tid&63, dg = tid>>6 (8 d-groups of 64). 64 W loads per thread,
//   fully unrolled, all L2-hits after the kernel-1 prefetch.
// ---------------------------------------------------------------------------
__global__ void __launch_bounds__(512) gemv_combine_kernel(
    const float* __restrict__ W, const float* __restrict__ bias,
    float* __restrict__ out)
{
    const int blk  = blockIdx.x;
    const int b    = blk >> 3;        // batch
    const int nt   = blk & 7;         // 64-wide n tile
    const int tid  = threadIdx.x;
    const int nloc = tid & 63;
    const int dg   = tid >> 6;        // d-group 0..7

    __shared__ float smd[D];
    {
        const float inv = 1.0f / (float)L;
        float v = g_part[0 * B * D + b * D + tid]
                + g_part[1 * B * D + b * D + tid]
                + g_part[2 * B * D + b * D + tid]
                + g_part[3 * B * D + b * D + tid];
        smd[tid] = v * inv;
    }
    __syncthreads();

    const int n = nt * 64 + nloc;
    const float* Wp = W + (size_t)(dg * 64) * NN + n;

    float u = 0.f;
    #pragma unroll
    for (int d = 0; d < 64; d++)
        u = fmaf(smd[dg * 64 + d], __ldg(Wp + (size_t)d * NN), u);

    __shared__ float su[512];
    su[tid] = u;
    __syncthreads();

    if (tid < 64) {
        float t = su[tid]       + su[tid + 64]  + su[tid + 128] + su[tid + 192]
                + su[tid + 256] + su[tid + 320] + su[tid + 384] + su[tid + 448];
        float bb = bias[nt * 64 + tid];
        out[b * NN + nt * 64 + tid] =
            0.5f * (fmaxf(t + bb, 0.f) + fmaxf(bb - t, 0.f));
    }
}

extern "C" void kernel_launch(void* const* d_in, const int* in_sizes, int n_in,
                              void* d_out, int out_size)
{
    const float* gi   = (const float*)d_in[0];   // i     [B, L, D]
    const float* gj   = (const float*)d_in[1];   // j     [B, L, D]
    const float* W    = (const float*)d_in[2];   // W_agg [D, NN]
    const float* bias = (const float*)d_in[3];   // b_agg [NN]
    float* out = (float*)d_out;                  // [B, NN]

    mean_diff_kernel<<<B * 8 * 4, 256>>>(gi, gj, W);
    gemv_combine_kernel<<<B * 8, 512>>>(W, bias, out);
}